// round 2
// baseline (speedup 1.0000x reference)
#include <cuda_runtime.h>
#include <cuda_bf16.h>
#include <cstddef>

#define N_NODES 50000
#define N_EDGES 800000
#define NFEAT 128
#define NHID 256
#define NCLASS 64

// ---- device scratch (static, no allocation) ----
__device__ int   g_is64;
__device__ float g_cnt [N_NODES];
__device__ float g_inv [N_NODES];
__device__ float g_sumx[(size_t)N_NODES * NFEAT];   // segment_sum of x
__device__ float g_h   [(size_t)N_NODES * NHID];    // layer1 output
__device__ float g_p2  [(size_t)N_NODES * NCLASS];  // h @ W2_neigh
__device__ float g_sump[(size_t)N_NODES * NCLASS];  // segment_sum of p2

// Detect whether edge_index buffer is int64 or int32.
// int64 values are < 50000, so every odd 32-bit word (high half, LE) is 0.
__global__ void detect_kernel(const int* __restrict__ ei32) {
    int allz = 1;
    #pragma unroll
    for (int i = 0; i < 32; ++i) {
        if (ei32[2 * i + 1] != 0) { allz = 0; break; }
    }
    g_is64 = allz;
}

__device__ __forceinline__ int load_idx(const void* __restrict__ ei, long long pos, int is64) {
    if (is64) return (int)((const long long*)ei)[pos];
    return ((const int*)ei)[pos];
}

// ---------------------------------------------------------------------------
__global__ void zero_kernel() {
    size_t i = (size_t)blockIdx.x * blockDim.x + threadIdx.x;
    const size_t n0 = N_NODES;
    const size_t n1 = n0 + (size_t)N_NODES * NFEAT;
    const size_t n2 = n1 + (size_t)N_NODES * NCLASS;
    if (i < n0)       g_cnt[i] = 0.f;
    else if (i < n1)  g_sumx[i - n0] = 0.f;
    else if (i < n2)  g_sump[i - n1] = 0.f;
}

__global__ void count_kernel(const void* __restrict__ ei) {
    int e = blockIdx.x * blockDim.x + threadIdx.x;
    if (e < N_EDGES) {
        int d = load_idx(ei, (long long)N_EDGES + e, g_is64);
        atomicAdd(&g_cnt[d], 1.0f);
    }
}

__global__ void inv_kernel() {
    int n = blockIdx.x * blockDim.x + threadIdx.x;
    if (n < N_NODES) g_inv[n] = 1.0f / fmaxf(g_cnt[n], 1.0f);
}

// one warp per edge: gather x[src][0:128] (float4/lane), scatter-add to sumx[dst]
__global__ void scatter_x_kernel(const float* __restrict__ x,
                                 const void* __restrict__ ei) {
    int idx  = blockIdx.x * blockDim.x + threadIdx.x;
    int e    = idx >> 5;
    int lane = idx & 31;
    if (e >= N_EDGES) return;
    int is64 = g_is64;
    int s = load_idx(ei, e, is64);
    int d = load_idx(ei, (long long)N_EDGES + e, is64);
    const float4 v = *(const float4*)(x + (size_t)s * NFEAT + lane * 4);
    float* o = g_sumx + (size_t)d * NFEAT + lane * 4;
    atomicAdd(o + 0, v.x);
    atomicAdd(o + 1, v.y);
    atomicAdd(o + 2, v.z);
    atomicAdd(o + 3, v.w);
}

// 16 threads per edge: gather p2[src][0:64], scatter-add to sump[dst]
__global__ void scatter_p_kernel(const void* __restrict__ ei) {
    int idx = blockIdx.x * blockDim.x + threadIdx.x;
    int e = idx >> 4;
    int q = idx & 15;
    if (e >= N_EDGES) return;
    int is64 = g_is64;
    int s = load_idx(ei, e, is64);
    int d = load_idx(ei, (long long)N_EDGES + e, is64);
    const float4 v = *(const float4*)(g_p2 + (size_t)s * NCLASS + q * 4);
    float* o = g_sump + (size_t)d * NCLASS + q * 4;
    atomicAdd(o + 0, v.x);
    atomicAdd(o + 1, v.y);
    atomicAdd(o + 2, v.z);
    atomicAdd(o + 3, v.w);
}

// ---------------------------------------------------------------------------
// GEMM1: h = relu( (sumx * inv) @ W1n + x @ W1r + b1 )   [50000,128]x[128,256]
// BM=64, BN=64, BK=16, 256 threads, 4x4 microtile
__global__ __launch_bounds__(256)
void gemm1_kernel(const float* __restrict__ x,
                  const float* __restrict__ W1n,
                  const float* __restrict__ W1r,
                  const float* __restrict__ b1) {
    const int rowBase = blockIdx.x * 64;
    const int colBase = blockIdx.y * 64;
    const int tid = threadIdx.x;
    const int tx = tid & 15;      // 0..15 -> 4 cols each
    const int ty = tid >> 4;      // 0..15 -> 4 rows each

    __shared__ float As[16][64];
    __shared__ float Bs[16][68];

    float acc[4][4] = {};

    const int aRow = tid >> 2;        // 0..63
    const int aK4  = (tid & 3) * 4;   // 0,4,8,12
    const int bK   = tid >> 4;        // 0..15
    const int bC4  = (tid & 15) * 4;  // 0..60

    #pragma unroll
    for (int s = 0; s < 2; ++s) {
        const float* A = (s == 0) ? g_sumx : x;
        const float* B = (s == 0) ? W1n : W1r;
        for (int kk = 0; kk < NFEAT; kk += 16) {
            int gr = rowBase + aRow;
            float4 av = make_float4(0.f, 0.f, 0.f, 0.f);
            if (gr < N_NODES) {
                av = *(const float4*)(A + (size_t)gr * NFEAT + kk + aK4);
                if (s == 0) {
                    float iv = g_inv[gr];
                    av.x *= iv; av.y *= iv; av.z *= iv; av.w *= iv;
                }
            }
            As[aK4 + 0][aRow] = av.x;
            As[aK4 + 1][aRow] = av.y;
            As[aK4 + 2][aRow] = av.z;
            As[aK4 + 3][aRow] = av.w;

            float4 bv = *(const float4*)(B + (size_t)(kk + bK) * NHID + colBase + bC4);
            Bs[bK][bC4 + 0] = bv.x;
            Bs[bK][bC4 + 1] = bv.y;
            Bs[bK][bC4 + 2] = bv.z;
            Bs[bK][bC4 + 3] = bv.w;
            __syncthreads();

            #pragma unroll
            for (int k = 0; k < 16; ++k) {
                float ra[4], rb[4];
                #pragma unroll
                for (int i = 0; i < 4; ++i) { ra[i] = As[k][ty * 4 + i]; }
                #pragma unroll
                for (int j = 0; j < 4; ++j) { rb[j] = Bs[k][tx * 4 + j]; }
                #pragma unroll
                for (int i = 0; i < 4; ++i)
                    #pragma unroll
                    for (int j = 0; j < 4; ++j)
                        acc[i][j] += ra[i] * rb[j];
            }
            __syncthreads();
        }
    }

    #pragma unroll
    for (int i = 0; i < 4; ++i) {
        int gr = rowBase + ty * 4 + i;
        if (gr >= N_NODES) continue;
        #pragma unroll
        for (int j = 0; j < 4; ++j) {
            int gc = colBase + tx * 4 + j;
            float v = acc[i][j] + b1[gc];
            g_h[(size_t)gr * NHID + gc] = fmaxf(v, 0.f);
        }
    }
}

// ---------------------------------------------------------------------------
// GEMM2: cb=0 -> p2 = h @ W2n ; cb=1 -> out = h @ W2r + b2
// [50000,256] x [256,64], BM=64, BN=64, BK=16
__global__ __launch_bounds__(256)
void gemm2_kernel(const float* __restrict__ W2n,
                  const float* __restrict__ W2r,
                  const float* __restrict__ b2,
                  float* __restrict__ out) {
    const int rowBase = blockIdx.x * 64;
    const int cb = blockIdx.y;
    const float* B = cb ? W2r : W2n;
    const int tid = threadIdx.x;
    const int tx = tid & 15;
    const int ty = tid >> 4;

    __shared__ float As[16][64];
    __shared__ float Bs[16][68];

    float acc[4][4] = {};

    const int aRow = tid >> 2;
    const int aK4  = (tid & 3) * 4;
    const int bK   = tid >> 4;
    const int bC4  = (tid & 15) * 4;

    for (int kk = 0; kk < NHID; kk += 16) {
        int gr = rowBase + aRow;
        float4 av = make_float4(0.f, 0.f, 0.f, 0.f);
        if (gr < N_NODES)
            av = *(const float4*)(g_h + (size_t)gr * NHID + kk + aK4);
        As[aK4 + 0][aRow] = av.x;
        As[aK4 + 1][aRow] = av.y;
        As[aK4 + 2][aRow] = av.z;
        As[aK4 + 3][aRow] = av.w;

        float4 bv = *(const float4*)(B + (size_t)(kk + bK) * NCLASS + bC4);
        Bs[bK][bC4 + 0] = bv.x;
        Bs[bK][bC4 + 1] = bv.y;
        Bs[bK][bC4 + 2] = bv.z;
        Bs[bK][bC4 + 3] = bv.w;
        __syncthreads();

        #pragma unroll
        for (int k = 0; k < 16; ++k) {
            float ra[4], rb[4];
            #pragma unroll
            for (int i = 0; i < 4; ++i) { ra[i] = As[k][ty * 4 + i]; }
            #pragma unroll
            for (int j = 0; j < 4; ++j) { rb[j] = Bs[k][tx * 4 + j]; }
            #pragma unroll
            for (int i = 0; i < 4; ++i)
                #pragma unroll
                for (int j = 0; j < 4; ++j)
                    acc[i][j] += ra[i] * rb[j];
        }
        __syncthreads();
    }

    #pragma unroll
    for (int i = 0; i < 4; ++i) {
        int gr = rowBase + ty * 4 + i;
        if (gr >= N_NODES) continue;
        #pragma unroll
        for (int j = 0; j < 4; ++j) {
            int gc = tx * 4 + j;
            if (cb == 0) {
                g_p2[(size_t)gr * NCLASS + gc] = acc[i][j];
            } else {
                out[(size_t)gr * NCLASS + gc] = acc[i][j] + b2[gc];
            }
        }
    }
}

// out += sump * inv  (finalize mean-aggregated neighbor term of layer 2)
__global__ void fin_kernel(float* __restrict__ out) {
    int i = blockIdx.x * blockDim.x + threadIdx.x;
    if (i < N_NODES * NCLASS) {
        int n = i >> 6;  // / NCLASS
        out[i] += g_sump[i] * g_inv[n];
    }
}

// ---------------------------------------------------------------------------
extern "C" void kernel_launch(void* const* d_in, const int* in_sizes, int n_in,
                              void* d_out, int out_size) {
    const float* x   = (const float*)d_in[0];
    const void*  ei  = d_in[1];
    const float* W1n = (const float*)d_in[2];
    const float* W1r = (const float*)d_in[3];
    const float* b1  = (const float*)d_in[4];
    const float* W2n = (const float*)d_in[5];
    const float* W2r = (const float*)d_in[6];
    const float* b2  = (const float*)d_in[7];
    float* out = (float*)d_out;

    // 0) detect edge_index dtype (int32 vs int64)
    detect_kernel<<<1, 1>>>((const int*)ei);

    // 1) zero scratch
    {
        size_t total = (size_t)N_NODES + (size_t)N_NODES * NFEAT + (size_t)N_NODES * NCLASS;
        int blocks = (int)((total + 255) / 256);
        zero_kernel<<<blocks, 256>>>();
    }
    // 2) degree counts + inverse
    count_kernel<<<(N_EDGES + 255) / 256, 256>>>(ei);
    inv_kernel<<<(N_NODES + 255) / 256, 256>>>();
    // 3) scatter x into sumx (warp per edge)
    {
        long long threads = (long long)N_EDGES * 32;
        int blocks = (int)((threads + 255) / 256);
        scatter_x_kernel<<<blocks, 256>>>(x, ei);
    }
    // 4) layer1 fused GEMM + relu
    {
        dim3 grid((N_NODES + 63) / 64, NHID / 64);
        gemm1_kernel<<<grid, 256>>>(x, W1n, W1r, b1);
    }
    // 5) layer2 projections: p2 = h@W2n, out = h@W2r + b2
    {
        dim3 grid((N_NODES + 63) / 64, 2);
        gemm2_kernel<<<grid, 256>>>(W2n, W2r, b2, out);
    }
    // 6) scatter p2 into sump (16 threads per edge)
    {
        long long threads = (long long)N_EDGES * 16;
        int blocks = (int)((threads + 255) / 256);
        scatter_p_kernel<<<blocks, 256>>>(ei);
    }
    // 7) finalize: out += sump * inv
    fin_kernel<<<(N_NODES * NCLASS + 255) / 256, 256>>>(out);
}

// round 3
// speedup vs baseline: 1.6107x; 1.6107x over previous
#include <cuda_runtime.h>
#include <cuda_bf16.h>
#include <cstddef>

#define N_NODES 50000
#define N_EDGES 800000
#define NFEAT 128
#define NHID 256
#define NCLASS 64

// ---- device scratch (static, no allocation) ----
__device__ int   g_is64;
__device__ int   g_deg [N_NODES];
__device__ int   g_off [N_NODES + 1];
__device__ int   g_cur [N_NODES];
__device__ int   g_csr [N_EDGES];                    // src ids grouped by dst
__device__ float g_meanx[(size_t)N_NODES * NFEAT];   // mean of x over in-edges
__device__ float g_h    [(size_t)N_NODES * NHID];    // layer1 output
__device__ float g_p2   [(size_t)N_NODES * NCLASS];  // h @ W2_neigh

// Detect whether edge_index buffer is int64 or int32 (JAX int64 often demoted).
// int64 values < 50000 -> every odd 32-bit word is 0.
__global__ void detect_kernel(const int* __restrict__ ei32) {
    int allz = 1;
    #pragma unroll
    for (int i = 0; i < 32; ++i) {
        if (ei32[2 * i + 1] != 0) { allz = 0; break; }
    }
    g_is64 = allz;
}

__device__ __forceinline__ int load_idx(const void* __restrict__ ei, long long pos, int is64) {
    if (is64) return (int)((const long long*)ei)[pos];
    return ((const int*)ei)[pos];
}

// ---------------------------------------------------------------------------
// CSR build
__global__ void zero_deg_kernel() {
    int i = blockIdx.x * blockDim.x + threadIdx.x;
    if (i < N_NODES) g_deg[i] = 0;
}

__global__ void hist_kernel(const void* __restrict__ ei) {
    int e = blockIdx.x * blockDim.x + threadIdx.x;
    if (e < N_EDGES) {
        int d = load_idx(ei, (long long)N_EDGES + e, g_is64);
        atomicAdd(&g_deg[d], 1);
    }
}

// single-block exclusive scan over g_deg -> g_off, g_cur
__global__ void scan_kernel() {
    __shared__ int sh[1024];
    __shared__ int carry;
    int tid = threadIdx.x;
    if (tid == 0) carry = 0;
    __syncthreads();
    for (int base = 0; base < N_NODES; base += 1024) {
        int i = base + tid;
        int v = (i < N_NODES) ? g_deg[i] : 0;
        sh[tid] = v;
        __syncthreads();
        #pragma unroll
        for (int d = 1; d < 1024; d <<= 1) {
            int t = (tid >= d) ? sh[tid - d] : 0;
            __syncthreads();
            sh[tid] += t;
            __syncthreads();
        }
        int excl = sh[tid] - v + carry;
        if (i < N_NODES) { g_off[i] = excl; g_cur[i] = excl; }
        __syncthreads();
        if (tid == 1023) carry += sh[1023];
        __syncthreads();
    }
    if (tid == 0) g_off[N_NODES] = N_EDGES;
}

__global__ void fill_kernel(const void* __restrict__ ei) {
    int e = blockIdx.x * blockDim.x + threadIdx.x;
    if (e < N_EDGES) {
        int is64 = g_is64;
        int s = load_idx(ei, e, is64);
        int d = load_idx(ei, (long long)N_EDGES + e, is64);
        int pos = atomicAdd(&g_cur[d], 1);
        g_csr[pos] = s;
    }
}

// ---------------------------------------------------------------------------
// warp per node: meanx[n] = mean over in-edges of x[src]   (128 f / row, 4/lane)
__global__ void agg_x_kernel(const float* __restrict__ x) {
    int gi = blockIdx.x * blockDim.x + threadIdx.x;
    int n = gi >> 5;
    int lane = gi & 31;
    if (n >= N_NODES) return;
    int beg = g_off[n], end = g_off[n + 1];
    float4 acc = make_float4(0.f, 0.f, 0.f, 0.f);
    for (int i = beg; i < end; ++i) {
        int s = g_csr[i];
        const float4 v = *(const float4*)(x + (size_t)s * NFEAT + lane * 4);
        acc.x += v.x; acc.y += v.y; acc.z += v.z; acc.w += v.w;
    }
    float inv = 1.0f / fmaxf((float)(end - beg), 1.0f);
    acc.x *= inv; acc.y *= inv; acc.z *= inv; acc.w *= inv;
    *(float4*)(g_meanx + (size_t)n * NFEAT + lane * 4) = acc;
}

// warp per node: out[n] += mean over in-edges of p2[src]  (64 f / row, 2/lane)
__global__ void agg_p_kernel(float* __restrict__ out) {
    int gi = blockIdx.x * blockDim.x + threadIdx.x;
    int n = gi >> 5;
    int lane = gi & 31;
    if (n >= N_NODES) return;
    int beg = g_off[n], end = g_off[n + 1];
    float2 acc = make_float2(0.f, 0.f);
    for (int i = beg; i < end; ++i) {
        int s = g_csr[i];
        const float2 v = *(const float2*)(g_p2 + (size_t)s * NCLASS + lane * 2);
        acc.x += v.x; acc.y += v.y;
    }
    float inv = 1.0f / fmaxf((float)(end - beg), 1.0f);
    float* o = out + (size_t)n * NCLASS + lane * 2;
    o[0] += acc.x * inv;
    o[1] += acc.y * inv;
}

// ---------------------------------------------------------------------------
// GEMM1: h = relu( meanx @ W1n + x @ W1r + b1 )   [50000,128]x[128,256]
// BM=128, BN=64, BK=16, 256 threads, 8x4 microtile
__global__ __launch_bounds__(256)
void gemm1_kernel(const float* __restrict__ x,
                  const float* __restrict__ W1n,
                  const float* __restrict__ W1r,
                  const float* __restrict__ b1) {
    const int rowBase = blockIdx.x * 128;
    const int colBase = blockIdx.y * 64;
    const int tid = threadIdx.x;
    const int tx = tid & 15;      // 4 cols each
    const int ty = tid >> 4;      // 8 rows each

    __shared__ float As[16][128];
    __shared__ float Bs[16][72];

    float acc[8][4] = {};

    const int aRow = tid >> 2;        // 0..63
    const int aK4  = (tid & 3) * 4;   // 0,4,8,12
    const int bK   = tid >> 4;        // 0..15
    const int bC4  = (tid & 15) * 4;  // 0..60

    #pragma unroll
    for (int s = 0; s < 2; ++s) {
        const float* A = (s == 0) ? g_meanx : x;
        const float* B = (s == 0) ? W1n : W1r;
        for (int kk = 0; kk < NFEAT; kk += 16) {
            #pragma unroll
            for (int h = 0; h < 2; ++h) {
                int r = aRow + h * 64;
                int gr = rowBase + r;
                float4 av = make_float4(0.f, 0.f, 0.f, 0.f);
                if (gr < N_NODES)
                    av = *(const float4*)(A + (size_t)gr * NFEAT + kk + aK4);
                As[aK4 + 0][r] = av.x;
                As[aK4 + 1][r] = av.y;
                As[aK4 + 2][r] = av.z;
                As[aK4 + 3][r] = av.w;
            }
            float4 bv = *(const float4*)(B + (size_t)(kk + bK) * NHID + colBase + bC4);
            Bs[bK][bC4 + 0] = bv.x;
            Bs[bK][bC4 + 1] = bv.y;
            Bs[bK][bC4 + 2] = bv.z;
            Bs[bK][bC4 + 3] = bv.w;
            __syncthreads();

            #pragma unroll
            for (int k = 0; k < 16; ++k) {
                float4 a0 = *(const float4*)&As[k][ty * 8];
                float4 a1 = *(const float4*)&As[k][ty * 8 + 4];
                float4 b  = *(const float4*)&Bs[k][tx * 4];
                float ra[8] = {a0.x, a0.y, a0.z, a0.w, a1.x, a1.y, a1.z, a1.w};
                float rb[4] = {b.x, b.y, b.z, b.w};
                #pragma unroll
                for (int i = 0; i < 8; ++i)
                    #pragma unroll
                    for (int j = 0; j < 4; ++j)
                        acc[i][j] += ra[i] * rb[j];
            }
            __syncthreads();
        }
    }

    #pragma unroll
    for (int i = 0; i < 8; ++i) {
        int gr = rowBase + ty * 8 + i;
        if (gr >= N_NODES) continue;
        #pragma unroll
        for (int j = 0; j < 4; ++j) {
            int gc = colBase + tx * 4 + j;
            float v = acc[i][j] + b1[gc];
            g_h[(size_t)gr * NHID + gc] = fmaxf(v, 0.f);
        }
    }
}

// ---------------------------------------------------------------------------
// GEMM2: cb=0 -> p2 = h @ W2n ; cb=1 -> out = h @ W2r + b2
// [50000,256] x [256,64], BM=128, BN=64, BK=16, 8x4 microtile
__global__ __launch_bounds__(256)
void gemm2_kernel(const float* __restrict__ W2n,
                  const float* __restrict__ W2r,
                  const float* __restrict__ b2,
                  float* __restrict__ out) {
    const int rowBase = blockIdx.x * 128;
    const int cb = blockIdx.y;
    const float* B = cb ? W2r : W2n;
    const int tid = threadIdx.x;
    const int tx = tid & 15;
    const int ty = tid >> 4;

    __shared__ float As[16][128];
    __shared__ float Bs[16][72];

    float acc[8][4] = {};

    const int aRow = tid >> 2;
    const int aK4  = (tid & 3) * 4;
    const int bK   = tid >> 4;
    const int bC4  = (tid & 15) * 4;

    for (int kk = 0; kk < NHID; kk += 16) {
        #pragma unroll
        for (int h = 0; h < 2; ++h) {
            int r = aRow + h * 64;
            int gr = rowBase + r;
            float4 av = make_float4(0.f, 0.f, 0.f, 0.f);
            if (gr < N_NODES)
                av = *(const float4*)(g_h + (size_t)gr * NHID + kk + aK4);
            As[aK4 + 0][r] = av.x;
            As[aK4 + 1][r] = av.y;
            As[aK4 + 2][r] = av.z;
            As[aK4 + 3][r] = av.w;
        }
        float4 bv = *(const float4*)(B + (size_t)(kk + bK) * NCLASS + bC4);
        Bs[bK][bC4 + 0] = bv.x;
        Bs[bK][bC4 + 1] = bv.y;
        Bs[bK][bC4 + 2] = bv.z;
        Bs[bK][bC4 + 3] = bv.w;
        __syncthreads();

        #pragma unroll
        for (int k = 0; k < 16; ++k) {
            float4 a0 = *(const float4*)&As[k][ty * 8];
            float4 a1 = *(const float4*)&As[k][ty * 8 + 4];
            float4 b  = *(const float4*)&Bs[k][tx * 4];
            float ra[8] = {a0.x, a0.y, a0.z, a0.w, a1.x, a1.y, a1.z, a1.w};
            float rb[4] = {b.x, b.y, b.z, b.w};
            #pragma unroll
            for (int i = 0; i < 8; ++i)
                #pragma unroll
                for (int j = 0; j < 4; ++j)
                    acc[i][j] += ra[i] * rb[j];
        }
        __syncthreads();
    }

    #pragma unroll
    for (int i = 0; i < 8; ++i) {
        int gr = rowBase + ty * 8 + i;
        if (gr >= N_NODES) continue;
        #pragma unroll
        for (int j = 0; j < 4; ++j) {
            int gc = tx * 4 + j;
            if (cb == 0) {
                g_p2[(size_t)gr * NCLASS + gc] = acc[i][j];
            } else {
                out[(size_t)gr * NCLASS + gc] = acc[i][j] + b2[gc];
            }
        }
    }
}

// ---------------------------------------------------------------------------
extern "C" void kernel_launch(void* const* d_in, const int* in_sizes, int n_in,
                              void* d_out, int out_size) {
    const float* x   = (const float*)d_in[0];
    const void*  ei  = d_in[1];
    const float* W1n = (const float*)d_in[2];
    const float* W1r = (const float*)d_in[3];
    const float* b1  = (const float*)d_in[4];
    const float* W2n = (const float*)d_in[5];
    const float* W2r = (const float*)d_in[6];
    const float* b2  = (const float*)d_in[7];
    float* out = (float*)d_out;

    // 0) dtype detect + CSR build
    detect_kernel<<<1, 1>>>((const int*)ei);
    zero_deg_kernel<<<(N_NODES + 255) / 256, 256>>>();
    hist_kernel<<<(N_EDGES + 255) / 256, 256>>>(ei);
    scan_kernel<<<1, 1024>>>();
    fill_kernel<<<(N_EDGES + 255) / 256, 256>>>(ei);

    // 1) layer1 aggregation (gather, warp per node)
    {
        long long threads = (long long)N_NODES * 32;
        agg_x_kernel<<<(int)((threads + 255) / 256), 256>>>(x);
    }
    // 2) layer1 fused GEMM + relu
    {
        dim3 grid((N_NODES + 127) / 128, NHID / 64);
        gemm1_kernel<<<grid, 256>>>(x, W1n, W1r, b1);
    }
    // 3) layer2 projections: p2 = h@W2n, out = h@W2r + b2
    {
        dim3 grid((N_NODES + 127) / 128, 2);
        gemm2_kernel<<<grid, 256>>>(W2n, W2r, b2, out);
    }
    // 4) layer2 aggregation: out += mean(p2 over in-edges)
    {
        long long threads = (long long)N_NODES * 32;
        agg_p_kernel<<<(int)((threads + 255) / 256), 256>>>(out);
    }
}